// round 2
// baseline (speedup 1.0000x reference)
#include <cuda_runtime.h>
#include <cstdint>

#define BROWS 64
#define L 16384
#define NT 512
#define CHUNK 32          // L / NT
#define NIMF 6
#define MAXIT 12
#define LP (L + (L >> 5)) // padded length (pad 1 float per 32 to kill bank conflicts)
#define PH(i) ((i) + ((i) >> 5))

// -------- device-global scratch (allocation-free contract) --------
__device__ float    g_res[BROWS * L];
__device__ double   g_part[2][BROWS][4];
__device__ unsigned g_count = 0;

__device__ __forceinline__ float negInf() { return __int_as_float(0xff800000); }
__device__ __forceinline__ float posInf() { return __int_as_float(0x7f800000); }

// -------- grid barrier: all 64 CTAs co-resident (1 wave), monotonic counter --------
__device__ __forceinline__ void gbar(unsigned* s_gen) {
    __syncthreads();
    if (threadIdx.x == 0) {
        unsigned g = ++(*s_gen);
        __threadfence();
        atomicAdd(&g_count, 1u);
        volatile unsigned* vc = &g_count;
        while (*vc < (unsigned)BROWS * g) { __nanosleep(32); }
        __threadfence();
    }
    __syncthreads();
}

// -------- block scans over 512 per-thread chunk aggregates --------
__device__ __forceinline__ int excl_prefix_max_i(int v, int* wbuf) {
    int lane = threadIdx.x & 31, wid = threadIdx.x >> 5;
    int incl = v;
#pragma unroll
    for (int d = 1; d < 32; d <<= 1) {
        int u = __shfl_up_sync(0xffffffffu, incl, d);
        if (lane >= d) incl = max(incl, u);
    }
    if (lane == 31) wbuf[wid] = incl;
    __syncthreads();
    if (wid == 0) {
        int w = (lane < 16) ? wbuf[lane] : -1;
#pragma unroll
        for (int d = 1; d < 16; d <<= 1) {
            int u = __shfl_up_sync(0xffffffffu, w, d);
            if (lane >= d) w = max(w, u);
        }
        if (lane < 16) wbuf[lane] = w;
    }
    __syncthreads();
    int woff = (wid > 0) ? wbuf[wid - 1] : -1;
    int lex  = __shfl_up_sync(0xffffffffu, incl, 1);
    int ex   = (lane > 0) ? max(woff, lex) : woff;
    __syncthreads();
    return ex;
}

__device__ __forceinline__ int excl_suffix_min_i(int v, int* wbuf) {
    int lane = threadIdx.x & 31, wid = threadIdx.x >> 5;
    int incl = v;
#pragma unroll
    for (int d = 1; d < 32; d <<= 1) {
        int u = __shfl_down_sync(0xffffffffu, incl, d);
        if (lane + d < 32) incl = min(incl, u);
    }
    if (lane == 0) wbuf[wid] = incl;
    __syncthreads();
    if (wid == 0) {
        int w = (lane < 16) ? wbuf[lane] : L;
#pragma unroll
        for (int d = 1; d < 16; d <<= 1) {
            int u = __shfl_down_sync(0xffffffffu, w, d);
            if (lane + d < 16) w = min(w, u);
        }
        if (lane < 16) wbuf[lane] = w;
    }
    __syncthreads();
    int woff = (wid < 15) ? wbuf[wid + 1] : L;
    int lex  = __shfl_down_sync(0xffffffffu, incl, 1);
    int ex   = (lane < 31) ? min(woff, lex) : woff;
    __syncthreads();
    return ex;
}

__device__ __forceinline__ float excl_prefix_max_f(float v, float* wbuf) {
    int lane = threadIdx.x & 31, wid = threadIdx.x >> 5;
    float incl = v;
#pragma unroll
    for (int d = 1; d < 32; d <<= 1) {
        float u = __shfl_up_sync(0xffffffffu, incl, d);
        if (lane >= d) incl = fmaxf(incl, u);
    }
    if (lane == 31) wbuf[wid] = incl;
    __syncthreads();
    if (wid == 0) {
        float w = (lane < 16) ? wbuf[lane] : negInf();
#pragma unroll
        for (int d = 1; d < 16; d <<= 1) {
            float u = __shfl_up_sync(0xffffffffu, w, d);
            if (lane >= d) w = fmaxf(w, u);
        }
        if (lane < 16) wbuf[lane] = w;
    }
    __syncthreads();
    float woff = (wid > 0) ? wbuf[wid - 1] : negInf();
    float lex  = __shfl_up_sync(0xffffffffu, incl, 1);
    float ex   = (lane > 0) ? fmaxf(woff, lex) : woff;
    __syncthreads();
    return ex;
}

__device__ __forceinline__ float excl_prefix_min_f(float v, float* wbuf) {
    int lane = threadIdx.x & 31, wid = threadIdx.x >> 5;
    float incl = v;
#pragma unroll
    for (int d = 1; d < 32; d <<= 1) {
        float u = __shfl_up_sync(0xffffffffu, incl, d);
        if (lane >= d) incl = fminf(incl, u);
    }
    if (lane == 31) wbuf[wid] = incl;
    __syncthreads();
    if (wid == 0) {
        float w = (lane < 16) ? wbuf[lane] : posInf();
#pragma unroll
        for (int d = 1; d < 16; d <<= 1) {
            float u = __shfl_up_sync(0xffffffffu, w, d);
            if (lane >= d) w = fminf(w, u);
        }
        if (lane < 16) wbuf[lane] = w;
    }
    __syncthreads();
    float woff = (wid > 0) ? wbuf[wid - 1] : posInf();
    float lex  = __shfl_up_sync(0xffffffffu, incl, 1);
    float ex   = (lane > 0) ? fminf(woff, lex) : woff;
    __syncthreads();
    return ex;
}

__device__ __forceinline__ int block_sum_i(int v, int* wbuf) {
#pragma unroll
    for (int d = 16; d; d >>= 1) v += __shfl_down_sync(0xffffffffu, v, d);
    int lane = threadIdx.x & 31, wid = threadIdx.x >> 5;
    if (lane == 0) wbuf[wid] = v;
    __syncthreads();
    if (threadIdx.x < 32) {
        int w = (threadIdx.x < 16) ? wbuf[threadIdx.x] : 0;
#pragma unroll
        for (int d = 8; d; d >>= 1) w += __shfl_down_sync(0xffffffffu, w, d);
        if (threadIdx.x == 0) wbuf[0] = w;
    }
    __syncthreads();
    int r = wbuf[0];
    __syncthreads();
    return r;
}

__device__ __forceinline__ double block_sum_d(double v, double* wbuf) {
#pragma unroll
    for (int d = 16; d; d >>= 1) v += __shfl_down_sync(0xffffffffu, v, d);
    int lane = threadIdx.x & 31, wid = threadIdx.x >> 5;
    if (lane == 0) wbuf[wid] = v;
    __syncthreads();
    if (threadIdx.x < 32) {
        double w = (threadIdx.x < 16) ? wbuf[threadIdx.x] : 0.0;
#pragma unroll
        for (int d = 8; d; d >>= 1) w += __shfl_down_sync(0xffffffffu, w, d);
        if (threadIdx.x == 0) wbuf[0] = w;
    }
    __syncthreads();
    double r = wbuf[0];
    __syncthreads();
    return r;
}

// -------- one envelope pass: upper writes mean = envU; lower does mean = 0.5*(mean + envL) --------
template <bool UPPER>
__device__ void env_pass(const float* h, float* mean, unsigned short* nxb,
                         int* ibuf, float* fbuf) {
    const int t  = threadIdx.x;
    const int lo = t * CHUNK, hi = lo + CHUNK;

    // Walk A (reverse): chunk-local suffix-min of masked index into nxb,
    // plus chunk aggregates: run (chunk min), cmax (chunk max masked), cnt (peaks).
    int run = L, cmax = -1, cnt = 0;
    float bb = h[PH(hi - 1)];
    float cc = (hi < L) ? h[PH(hi)] : 0.f;
    for (int i = hi - 1; i >= lo; --i) {
        float aa = (i > 0) ? h[PH(i - 1)] : 0.f;
        bool pk;
        if (UPPER) pk = (i > 0) && (i < L - 1) && (aa < bb) && (bb > cc);
        else       pk = (i > 0) && (i < L - 1) && (aa > bb) && (bb < cc);
        if (pk) { run = i; if (cmax < 0) cmax = i; cnt++; }
        nxb[PH(i)] = (unsigned short)run;
        cc = bb; bb = aa;
    }

    int off_nxt  = excl_suffix_min_i(run, ibuf);   // min masked idx among threads > t
    int off_last = excl_prefix_max_i(cmax, ibuf);  // max masked idx among threads < t
    int total    = block_sum_i(cnt, ibuf);         // peaks in row

    if (total >= 2) {
        // Walk B (forward): running last-peak + interpolation
        int runl = off_last;
        float a2 = (lo > 0) ? h[PH(lo - 1)] : 0.f;
        float b2 = h[PH(lo)];
        for (int i = lo; i < hi; ++i) {
            float c2 = (i + 1 < L) ? h[PH(i + 1)] : 0.f;
            bool pk;
            if (UPPER) pk = (i > 0) && (i < L - 1) && (a2 < b2) && (b2 > c2);
            else       pk = (i > 0) && (i < L - 1) && (a2 > b2) && (b2 < c2);
            if (pk) runl = i;
            int nxv = min((int)nxb[PH(i)], off_nxt);
            int la  = runl;
            float vl = h[PH(max(la, 0))];
            float vr = h[PH(min(nxv, L - 1))];
            int denom = nxv - la;
            float env;
            if (denom > 0) env = vl + ((float)(i - la) / (float)denom) * (vr - vl);
            else           env = vl;
            if (la < 0)   env = vr;   // left of first peak
            if (nxv >= L) env = vl;   // right of last peak
            if (UPPER) mean[PH(i)] = env;
            else { float u = mean[PH(i)]; mean[PH(i)] = 0.5f * (u + env); }
            a2 = b2; b2 = c2;
        }
    } else {
        // fallback: running cummax / cummin of h
        float agg = UPPER ? negInf() : posInf();
        for (int i = lo; i < hi; ++i) {
            float hv = h[PH(i)];
            agg = UPPER ? fmaxf(agg, hv) : fminf(agg, hv);
        }
        float off  = UPPER ? excl_prefix_max_f(agg, fbuf) : excl_prefix_min_f(agg, fbuf);
        float runv = off;
        for (int i = lo; i < hi; ++i) {
            float hv = h[PH(i)];
            runv = UPPER ? fmaxf(runv, hv) : fminf(runv, hv);
            if (UPPER) mean[PH(i)] = runv;
            else { float u = mean[PH(i)]; mean[PH(i)] = 0.5f * (u + runv); }
        }
    }
    __syncthreads();
}

__global__ __launch_bounds__(NT, 1)
void emd_kernel(const float* __restrict__ x, float* __restrict__ out) {
    extern __shared__ unsigned char dynsm[];
    float*          h   = (float*)dynsm;                       // LP floats
    float*          mn  = h + LP;                              // LP floats
    unsigned short* nxb = (unsigned short*)(mn + LP);          // LP u16

    __shared__ int      s_i[17];
    __shared__ float    s_f[17];
    __shared__ double   s_d[17];
    __shared__ unsigned s_gen;
    __shared__ int      s_flag;

    const int t   = threadIdx.x;
    const int row = blockIdx.x;
    if (t == 0) s_gen = 0u;

    const float* xr   = x + (size_t)row * L;
    float*       resr = g_res + (size_t)row * L;

    // res = x (re-initialized every launch: deterministic)
    for (int i = t; i < L; i += NT) resr[i] = xr[i];

    int  phase      = 0;
    bool outer_done = false;

    for (int im = 0; im < NIMF; ++im) {
        float* outim = out + ((size_t)im * BROWS + row) * L;
        if (outer_done) {
            for (int i = t; i < L; i += NT) outim[i] = 0.f;
            continue;  // uniform across the whole grid -> barrier counts stay consistent
        }

        // h = res
        for (int i = t; i < L; i += NT) h[PH(i)] = resr[i];
        __syncthreads();

        // ---- sifting ----
        for (int it = 0; it < MAXIT; ++it) {
            env_pass<true >(h, mn, nxb, s_i, s_f);
            env_pass<false>(h, mn, nxb, s_i, s_f);

            double sm = 0.0, sh2 = 0.0;
            for (int i = t; i < L; i += NT) {
                float m = mn[PH(i)], hv = h[PH(i)];
                sm  += (double)m * (double)m;
                sh2 += (double)hv * (double)hv;
            }
            sm  = block_sum_d(sm, s_d);
            sh2 = block_sum_d(sh2, s_d);
            if (t == 0) {
                g_part[phase & 1][row][0] = sm;
                g_part[phase & 1][row][1] = sh2;
            }
            gbar(&s_gen);
            if (t == 0) {
                volatile double* vp = &g_part[phase & 1][0][0];
                double A = 0.0, Bs = 0.0;
                for (int r = 0; r < BROWS; ++r) { A += vp[r * 4]; Bs += vp[r * 4 + 1]; }
                double sd = A / (Bs + 1e-8);
                s_flag = (sd < 0.05) ? 1 : 0;
            }
            phase++;
            __syncthreads();
            if (s_flag) break;       // global convergence: h stays (reference keeps h, not h-mean)
            for (int i = t; i < L; i += NT) h[PH(i)] -= mn[PH(i)];
            __syncthreads();
        }

        // ---- emit IMF, update residual, global flatness check ----
        double Sd = 0.0, Sd2 = 0.0, Sr = 0.0, Sr2 = 0.0;
        for (int i = t; i < L; i += NT) {
            float hv = h[PH(i)];
            float nr = resr[i] - hv;
            outim[i]  = hv;
            resr[i]   = nr;
            mn[PH(i)] = nr;                 // reuse mean buffer for diff pass
            Sr  += (double)nr;
            Sr2 += (double)nr * (double)nr;
        }
        __syncthreads();
        for (int i = t; i < L; i += NT) {
            if (i < L - 1) {
                float d = mn[PH(i + 1)] - mn[PH(i)];
                Sd  += (double)d;
                Sd2 += (double)d * (double)d;
            }
        }
        Sd  = block_sum_d(Sd, s_d);
        Sd2 = block_sum_d(Sd2, s_d);
        Sr  = block_sum_d(Sr, s_d);
        Sr2 = block_sum_d(Sr2, s_d);
        if (t == 0) {
            double* p = &g_part[phase & 1][row][0];
            p[0] = Sd; p[1] = Sd2; p[2] = Sr; p[3] = Sr2;
        }
        gbar(&s_gen);
        if (t == 0) {
            volatile double* vp = &g_part[phase & 1][0][0];
            double a = 0.0, b = 0.0, c = 0.0, e = 0.0;
            for (int r = 0; r < BROWS; ++r) {
                a += vp[r * 4]; b += vp[r * 4 + 1]; c += vp[r * 4 + 2]; e += vp[r * 4 + 3];
            }
            double ndv = (double)BROWS * (double)(L - 1);
            double nrv = (double)BROWS * (double)L;
            double vard = (b - a * a / ndv) / (ndv - 1.0);
            double varr = (e - c * c / nrv) / (nrv - 1.0);
            s_flag = (vard < 0.05 * varr) ? 1 : 0;
        }
        phase++;
        __syncthreads();
        if (s_flag) outer_done = true;
    }

    // final residual
    float* outres = out + ((size_t)NIMF * BROWS + row) * L;
    for (int i = t; i < L; i += NT) outres[i] = resr[i];

    // reset barrier counter for the next (graph-replayed) launch
    gbar(&s_gen);
    if (row == 0 && t == 0) g_count = 0u;
}

extern "C" void kernel_launch(void* const* d_in, const int* in_sizes, int n_in,
                              void* d_out, int out_size) {
    (void)in_sizes; (void)n_in; (void)out_size;
    const size_t shmem = (size_t)(2 * LP) * sizeof(float) + (size_t)LP * sizeof(unsigned short);
    cudaFuncSetAttribute(emd_kernel, cudaFuncAttributeMaxDynamicSharedMemorySize, (int)shmem);
    emd_kernel<<<BROWS, NT, shmem>>>((const float*)d_in[0], (float*)d_out);
}

// round 3
// speedup vs baseline: 1.7740x; 1.7740x over previous
#include <cuda_runtime.h>
#include <cstdint>

#define BROWS 64
#define L 16384
#define NT 1024
#define NW 32
#define CHUNK 16          // L / NT
#define NIMF 6
#define MAXIT 12
#define LP (L + (L >> 5)) // padded length (pad 1 float per 32 to kill bank conflicts)
#define PH(i) ((i) + ((i) >> 5))

// -------- device-global scratch (allocation-free contract) --------
__device__ float    g_res[BROWS * L];
__device__ double   g_part[2][BROWS][4];
__device__ unsigned g_count = 0;

__device__ __forceinline__ float negInf() { return __int_as_float(0xff800000); }
__device__ __forceinline__ float posInf() { return __int_as_float(0x7f800000); }

// -------- grid barrier: all 64 CTAs co-resident (1 wave), monotonic counter --------
__device__ __forceinline__ void gbar(unsigned* s_gen) {
    __syncthreads();
    if (threadIdx.x == 0) {
        unsigned g = ++(*s_gen);
        __threadfence();
        atomicAdd(&g_count, 1u);
        volatile unsigned* vc = &g_count;
        while (*vc < (unsigned)BROWS * g) { __nanosleep(20); }
        __threadfence();
    }
    __syncthreads();
}

// -------- packed-u16 exclusive suffix-min over NT threads (both halfwords independent) --------
__device__ __forceinline__ unsigned sufmin2_excl(unsigned v, unsigned* wbuf) {
    const int lane = threadIdx.x & 31, wid = threadIdx.x >> 5;
    unsigned incl = v;
#pragma unroll
    for (int d = 1; d < 32; d <<= 1) {
        unsigned u = __shfl_down_sync(0xffffffffu, incl, d);
        if (lane + d < 32) incl = __vminu2(incl, u);
    }
    if (lane == 0) wbuf[wid] = incl;
    __syncthreads();
    if (wid == 0) {
        unsigned w = wbuf[lane];
#pragma unroll
        for (int d = 1; d < 32; d <<= 1) {
            unsigned u = __shfl_down_sync(0xffffffffu, w, d);
            if (lane + d < 32) w = __vminu2(w, u);
        }
        wbuf[lane] = w;
    }
    __syncthreads();
    unsigned woff = (wid < NW - 1) ? wbuf[wid + 1] : 0x40004000u;  // (L, L) identity
    unsigned lex  = __shfl_down_sync(0xffffffffu, incl, 1);
    unsigned ex   = (lane < 31) ? __vminu2(woff, lex) : woff;
    __syncthreads();
    return ex;
}

// -------- packed-s16 exclusive prefix-max over NT threads --------
__device__ __forceinline__ unsigned premax2_excl(unsigned v, unsigned* wbuf) {
    const int lane = threadIdx.x & 31, wid = threadIdx.x >> 5;
    unsigned incl = v;
#pragma unroll
    for (int d = 1; d < 32; d <<= 1) {
        unsigned u = __shfl_up_sync(0xffffffffu, incl, d);
        if (lane >= d) incl = __vmaxs2(incl, u);
    }
    if (lane == 31) wbuf[wid] = incl;
    __syncthreads();
    if (wid == 0) {
        unsigned w = wbuf[lane];
#pragma unroll
        for (int d = 1; d < 32; d <<= 1) {
            unsigned u = __shfl_up_sync(0xffffffffu, w, d);
            if (lane >= d) w = __vmaxs2(w, u);
        }
        wbuf[lane] = w;
    }
    __syncthreads();
    unsigned woff = (wid > 0) ? wbuf[wid - 1] : 0xffffffffu;  // (-1, -1) identity
    unsigned lex  = __shfl_up_sync(0xffffffffu, incl, 1);
    unsigned ex   = (lane > 0) ? __vmaxs2(woff, lex) : woff;
    __syncthreads();
    return ex;
}

// -------- float exclusive prefix-max / prefix-min (rare fallback path) --------
__device__ __forceinline__ float pmax_f_excl(float v, float* wbuf) {
    const int lane = threadIdx.x & 31, wid = threadIdx.x >> 5;
    float incl = v;
#pragma unroll
    for (int d = 1; d < 32; d <<= 1) {
        float u = __shfl_up_sync(0xffffffffu, incl, d);
        if (lane >= d) incl = fmaxf(incl, u);
    }
    if (lane == 31) wbuf[wid] = incl;
    __syncthreads();
    if (wid == 0) {
        float w = wbuf[lane];
#pragma unroll
        for (int d = 1; d < 32; d <<= 1) {
            float u = __shfl_up_sync(0xffffffffu, w, d);
            if (lane >= d) w = fmaxf(w, u);
        }
        wbuf[lane] = w;
    }
    __syncthreads();
    float woff = (wid > 0) ? wbuf[wid - 1] : negInf();
    float lex  = __shfl_up_sync(0xffffffffu, incl, 1);
    float ex   = (lane > 0) ? fmaxf(woff, lex) : woff;
    __syncthreads();
    return ex;
}

__device__ __forceinline__ float pmin_f_excl(float v, float* wbuf) {
    const int lane = threadIdx.x & 31, wid = threadIdx.x >> 5;
    float incl = v;
#pragma unroll
    for (int d = 1; d < 32; d <<= 1) {
        float u = __shfl_up_sync(0xffffffffu, incl, d);
        if (lane >= d) incl = fminf(incl, u);
    }
    if (lane == 31) wbuf[wid] = incl;
    __syncthreads();
    if (wid == 0) {
        float w = wbuf[lane];
#pragma unroll
        for (int d = 1; d < 32; d <<= 1) {
            float u = __shfl_up_sync(0xffffffffu, w, d);
            if (lane >= d) w = fminf(w, u);
        }
        wbuf[lane] = w;
    }
    __syncthreads();
    float woff = (wid > 0) ? wbuf[wid - 1] : posInf();
    float lex  = __shfl_up_sync(0xffffffffu, incl, 1);
    float ex   = (lane > 0) ? fminf(woff, lex) : woff;
    __syncthreads();
    return ex;
}

// -------- packed u32 block sum (both halfwords; no cross-half carry: totals <= 8192) --------
__device__ __forceinline__ unsigned block_sum_u(unsigned v, unsigned* wbuf) {
#pragma unroll
    for (int d = 16; d; d >>= 1) v += __shfl_down_sync(0xffffffffu, v, d);
    const int lane = threadIdx.x & 31, wid = threadIdx.x >> 5;
    if (lane == 0) wbuf[wid] = v;
    __syncthreads();
    if (wid == 0) {
        unsigned w = wbuf[lane];
#pragma unroll
        for (int d = 16; d; d >>= 1) w += __shfl_down_sync(0xffffffffu, w, d);
        if (lane == 0) wbuf[0] = w;
    }
    __syncthreads();
    unsigned r = wbuf[0];
    __syncthreads();
    return r;
}

// -------- two doubles reduced in one pass of syncs --------
__device__ __forceinline__ void block_sum_d2(double& a, double& b, double* wbuf) {
#pragma unroll
    for (int d = 16; d; d >>= 1) {
        a += __shfl_down_sync(0xffffffffu, a, d);
        b += __shfl_down_sync(0xffffffffu, b, d);
    }
    const int lane = threadIdx.x & 31, wid = threadIdx.x >> 5;
    if (lane == 0) { wbuf[wid] = a; wbuf[NW + wid] = b; }
    __syncthreads();
    if (wid == 0) {
        double wa = wbuf[lane], wb = wbuf[NW + lane];
#pragma unroll
        for (int d = 16; d; d >>= 1) {
            wa += __shfl_down_sync(0xffffffffu, wa, d);
            wb += __shfl_down_sync(0xffffffffu, wb, d);
        }
        if (lane == 0) { wbuf[0] = wa; wbuf[NW] = wb; }
    }
    __syncthreads();
    a = wbuf[0]; b = wbuf[NW];
    __syncthreads();
}

// -------- one fused sifting pass: both envelopes + mean + (h - mean) + sd partials --------
__device__ void sift_pass(const float* __restrict__ hc, float* __restrict__ ho,
                          uint32_t* __restrict__ nxb,
                          unsigned* ubuf, float* fbuf,
                          double& o_sm, double& o_sh2)
{
    const int t  = threadIdx.x;
    const int lo = t * CHUNK, hi = lo + CHUNK;

    // ---- walk A (reverse): peak masks, within-chunk next-peak (packed), aggregates ----
    int run_u = L, run_l = L, cm_u = -1, cm_l = -1;
    unsigned cnt = 0;
    float chmax = negInf(), chmin = posInf();
    float bb = hc[PH(hi - 1)];
    float cc = (hi < L) ? hc[PH(hi)] : 0.f;
#pragma unroll
    for (int j = CHUNK - 1; j >= 0; --j) {
        int i = lo + j;
        float aa = (i > 0) ? hc[PH(i - 1)] : 0.f;
        bool inter = (i > 0) && (i < L - 1);
        bool pu = inter && (aa < bb) && (bb > cc);
        bool pl = inter && (aa > bb) && (bb < cc);
        if (pu) { run_u = i; if (cm_u < 0) cm_u = i; cnt += 1u; }
        if (pl) { run_l = i; if (cm_l < 0) cm_l = i; cnt += 0x10000u; }
        chmax = fmaxf(chmax, bb); chmin = fminf(chmin, bb);
        nxb[PH(i)] = (uint32_t)run_u | ((uint32_t)run_l << 16);
        cc = bb; bb = aa;
    }

    // ---- block collectives (packed, 3 total) ----
    unsigned offn = sufmin2_excl((unsigned)run_u | ((unsigned)run_l << 16), ubuf);
    unsigned offl = premax2_excl(((unsigned)cm_u & 0xffffu) | (((unsigned)cm_l & 0xffffu) << 16), ubuf);
    unsigned tot  = block_sum_u(cnt, ubuf);

    const int  off_nu = (int)(offn & 0xffffu);
    const int  off_nl = (int)(offn >> 16);
    const int  off_lu = (int)(short)(offl & 0xffffu);
    const int  off_ll = (int)(short)(offl >> 16);
    const bool few_u  = (tot & 0xffffu) < 2u;   // block-uniform
    const bool few_l  = (tot >> 16)    < 2u;    // block-uniform

    float runmax = negInf(), runmin = posInf();
    if (few_u) runmax = pmax_f_excl(chmax, fbuf);
    if (few_l) runmin = pmin_f_excl(chmin, fbuf);

    // ---- walk B (forward): envelopes, mean, h_next, sd partials ----
    int   runl_u = off_lu, runl_l = off_ll;
    float vl_u = hc[PH(max(runl_u, 0))];
    float vl_l = hc[PH(max(runl_l, 0))];
    int   cur_nu = -9, cur_nl = -9;
    float vr_u = 0.f, vr_l = 0.f;
    float acc_m = 0.f, acc_h = 0.f;

    float a2 = (lo > 0) ? hc[PH(lo - 1)] : 0.f;
    float b2 = hc[PH(lo)];
#pragma unroll 4
    for (int j = 0; j < CHUNK; ++j) {
        int i = lo + j;
        float c2 = (i + 1 < L) ? hc[PH(i + 1)] : 0.f;
        bool inter = (i > 0) && (i < L - 1);
        bool pu = inter && (a2 < b2) && (b2 > c2);
        bool pl = inter && (a2 > b2) && (b2 < c2);
        if (pu) { runl_u = i; vl_u = b2; }
        if (pl) { runl_l = i; vl_l = b2; }
        uint32_t pk = nxb[PH(i)];
        int nu = min((int)(pk & 0xffffu), off_nu);
        int nl = min((int)(pk >> 16),    off_nl);
        if (nu != cur_nu) { cur_nu = nu; vr_u = hc[PH(min(nu, L - 1))]; }
        if (nl != cur_nl) { cur_nl = nl; vr_l = hc[PH(min(nl, L - 1))]; }

        float eu;
        {
            int den = nu - runl_u;
            eu = (den > 0) ? vl_u + ((float)(i - runl_u) / (float)den) * (vr_u - vl_u) : vl_u;
            if (runl_u < 0) eu = vr_u;   // left of first peak
            if (nu >= L)    eu = vl_u;   // right of last peak
        }
        runmax = fmaxf(runmax, b2);
        if (few_u) eu = runmax;          // cummax fallback

        float el;
        {
            int den = nl - runl_l;
            el = (den > 0) ? vl_l + ((float)(i - runl_l) / (float)den) * (vr_l - vl_l) : vl_l;
            if (runl_l < 0) el = vr_l;
            if (nl >= L)    el = vl_l;
        }
        runmin = fminf(runmin, b2);
        if (few_l) el = runmin;          // cummin fallback

        float mean = 0.5f * (eu + el);
        ho[PH(i)]  = b2 - mean;
        acc_m += mean * mean;
        acc_h += b2 * b2;
        a2 = b2; b2 = c2;
    }
    o_sm  = (double)acc_m;
    o_sh2 = (double)acc_h;
}

__global__ void __launch_bounds__(NT, 1)
emd_kernel(const float* __restrict__ x, float* __restrict__ out)
{
    extern __shared__ unsigned char dynsm[];
    float*    bufA = (float*)dynsm;             // LP floats
    float*    bufB = bufA + LP;                 // LP floats
    uint32_t* nxb  = (uint32_t*)(bufB + LP);    // LP u32

    __shared__ unsigned s_u[NW + 1];
    __shared__ float    s_f[NW + 1];
    __shared__ double   s_d[2 * NW];
    __shared__ unsigned s_gen;
    __shared__ int      s_flag;

    const int t   = threadIdx.x;
    const int row = blockIdx.x;
    if (t == 0) s_gen = 0u;

    const float* xr   = x + (size_t)row * L;
    float*       resr = g_res + (size_t)row * L;

    // res = x (re-initialized every launch: deterministic)
    for (int i = t; i < L; i += NT) resr[i] = xr[i];

    int  phase      = 0;
    bool outer_done = false;

    for (int im = 0; im < NIMF; ++im) {
        float* outim = out + ((size_t)im * BROWS + row) * L;
        if (outer_done) {
            for (int i = t; i < L; i += NT) outim[i] = 0.f;
            continue;  // globally uniform -> barrier counts stay consistent
        }

        float* hc = bufA;
        float* ho = bufB;
        for (int i = t; i < L; i += NT) hc[PH(i)] = resr[i];
        __syncthreads();

        // ---- sifting (double-buffered) ----
        for (int it = 0; it < MAXIT; ++it) {
            double sm, sh2;
            sift_pass(hc, ho, nxb, s_u, s_f, sm, sh2);
            block_sum_d2(sm, sh2, s_d);
            if (t == 0) {
                g_part[phase & 1][row][0] = sm;
                g_part[phase & 1][row][1] = sh2;
            }
            gbar(&s_gen);
            if (t == 0) {
                volatile double* vp = &g_part[phase & 1][0][0];
                double A = 0.0, Bs = 0.0;
                for (int r = 0; r < BROWS; ++r) { A += vp[r * 4]; Bs += vp[r * 4 + 1]; }
                s_flag = (A / (Bs + 1e-8) < 0.05) ? 1 : 0;
            }
            phase++;
            __syncthreads();
            if (s_flag) break;            // converged: keep hc (pre-subtract), matching reference
            float* tmp = hc; hc = ho; ho = tmp;   // accept h - mean
        }

        // ---- emit IMF, update residual, global flatness check ----
        float acc_r = 0.f, acc_r2 = 0.f;
        for (int i = t; i < L; i += NT) {
            float hv = hc[PH(i)];
            float nr = resr[i] - hv;
            outim[i]  = hv;
            resr[i]   = nr;
            ho[PH(i)] = nr;               // scratch for diff pass
            acc_r  += nr;
            acc_r2 += nr * nr;
        }
        __syncthreads();
        float acc_d = 0.f, acc_d2 = 0.f;
        for (int i = t; i < L; i += NT) {
            if (i < L - 1) {
                float d = ho[PH(i + 1)] - ho[PH(i)];
                acc_d  += d;
                acc_d2 += d * d;
            }
        }
        double Sd = (double)acc_d, Sd2 = (double)acc_d2;
        double Sr = (double)acc_r, Sr2 = (double)acc_r2;
        block_sum_d2(Sd, Sd2, s_d);
        block_sum_d2(Sr, Sr2, s_d);
        if (t == 0) {
            double* p = &g_part[phase & 1][row][0];
            p[0] = Sd; p[1] = Sd2; p[2] = Sr; p[3] = Sr2;
        }
        gbar(&s_gen);
        if (t == 0) {
            volatile double* vp = &g_part[phase & 1][0][0];
            double a = 0.0, b = 0.0, c = 0.0, e = 0.0;
            for (int r = 0; r < BROWS; ++r) {
                a += vp[r * 4]; b += vp[r * 4 + 1]; c += vp[r * 4 + 2]; e += vp[r * 4 + 3];
            }
            double ndv = (double)BROWS * (double)(L - 1);
            double nrv = (double)BROWS * (double)L;
            double vard = (b - a * a / ndv) / (ndv - 1.0);
            double varr = (e - c * c / nrv) / (nrv - 1.0);
            s_flag = (vard < 0.05 * varr) ? 1 : 0;
        }
        phase++;
        __syncthreads();
        if (s_flag) outer_done = true;
    }

    // final residual
    float* outres = out + ((size_t)NIMF * BROWS + row) * L;
    for (int i = t; i < L; i += NT) outres[i] = resr[i];

    // reset barrier counter for the next (graph-replayed) launch
    gbar(&s_gen);
    if (row == 0 && t == 0) g_count = 0u;
}

extern "C" void kernel_launch(void* const* d_in, const int* in_sizes, int n_in,
                              void* d_out, int out_size) {
    (void)in_sizes; (void)n_in; (void)out_size;
    const size_t shmem = (size_t)(2 * LP) * sizeof(float) + (size_t)LP * sizeof(uint32_t);
    cudaFuncSetAttribute(emd_kernel, cudaFuncAttributeMaxDynamicSharedMemorySize, (int)shmem);
    emd_kernel<<<BROWS, NT, shmem>>>((const float*)d_in[0], (float*)d_out);
}